// round 11
// baseline (speedup 1.0000x reference)
#include <cuda_runtime.h>
#include <math.h>

#define EPSF 1e-4f
typedef unsigned long long u64;

__device__ __forceinline__ u64 pack2(float x){
  u64 r; unsigned xi = __float_as_uint(x);
  asm("mov.b64 %0, {%1, %1};" : "=l"(r) : "r"(xi));
  return r;
}
__device__ __forceinline__ void fma2(u64 &acc, u64 a, u64 b){
  asm("fma.rn.f32x2 %0, %1, %2, %0;" : "+l"(acc) : "l"(a), "l"(b));
}
__device__ __forceinline__ float2 unpack2(u64 v){
  unsigned lo, hi;
  asm("mov.b64 {%0, %1}, %2;" : "=r"(lo), "=r"(hi) : "l"(v));
  return make_float2(__uint_as_float(lo), __uint_as_float(hi));
}
__device__ __forceinline__ u64 packf2(float lo, float hi){
  u64 r;
  asm("mov.b64 %0, {%1, %2};" : "=l"(r) : "r"(__float_as_uint(lo)), "r"(__float_as_uint(hi)));
  return r;
}
__device__ __forceinline__ float rsum32(float v){
  #pragma unroll
  for (int o=16;o;o>>=1) v += __shfl_xor_sync(0xffffffffu, v, o);
  return v;
}
__device__ __forceinline__ float rsum16(float v){
  #pragma unroll
  for (int o=8;o;o>>=1) v += __shfl_xor_sync(0xffffffffu, v, o);
  return v;
}
__device__ __forceinline__ float rmax16(float v){
  #pragma unroll
  for (int o=8;o;o>>=1) v = fmaxf(v, __shfl_xor_sync(0xffffffffu, v, o));
  return v;
}
__device__ __forceinline__ float sigm(float x){ return 1.f/(1.f+expf(-x)); }
__device__ __forceinline__ float splus(float x){ return fmaxf(x,0.f)+log1pf(expf(-fabsf(x))); }
__device__ __forceinline__ unsigned s2u(const void* p){
  return (unsigned)__cvta_generic_to_shared(p);
}
#define CLUSTER_SYNC() do{ \
    asm volatile("barrier.cluster.arrive.aligned;" ::: "memory"); \
    asm volatile("barrier.cluster.wait.aligned;"   ::: "memory"); }while(0)

struct Smem {
  float sciT[260][4];
  float sh1T[128][4];
  float sct2[128][4];
  float sc[4][16][132];
  float smix[4][16][16];
  float satt[4][128];
  float sbuf[16][4][128];
  float ssp[4][16], smaM[4][16], sal[4][16], sgs[4][16];
  float ssq[4][16], sms[4][16], smm[4][16];
  float sraw[4][4][16];
  float sred[4][4][3];
  float snv[4], srl[4], sval[4];
  int   sidx[4];
};

__global__ void __launch_bounds__(512,1) __cluster_dims__(2,1,1) cfrm_kernel(
   const int* __restrict__ tokens, const float* __restrict__ emb,
   const float* __restrict__ ln_g, const float* __restrict__ ln_b,
   const float* __restrict__ w1, const float* __restrict__ b1,
   const float* __restrict__ w2, const float* __restrict__ b2,
   const float* __restrict__ gate_w, const float* __restrict__ gate_b,
   const float* __restrict__ assign_w, const float* __restrict__ assign_b,
   const float* __restrict__ nov_w, const float* __restrict__ nov_b,
   const float* __restrict__ relax_w, const float* __restrict__ relax_b,
   const float* __restrict__ cc_w, const float* __restrict__ cc_b,
   const float* __restrict__ cs_w, const float* __restrict__ cs_b,
   const float* __restrict__ md_w, const float* __restrict__ md_b,
   const float* __restrict__ att_w, const float* __restrict__ att_b,
   const float* __restrict__ cw1, const float* __restrict__ cb1,
   const float* __restrict__ cw2, const float* __restrict__ cb2,
   float* __restrict__ out)
{
  extern __shared__ __align__(128) char smem_raw[];
  Smem* S = (Smem*)smem_raw;

  const int tid  = threadIdx.x;
  const int g    = tid >> 7;
  const int ht   = tid & 127;
  const int lane = tid & 31;
  const int wg   = (tid >> 5) & 3;
  const int rank = (int)(blockIdx.x & 1);
  const int b    = (int)(blockIdx.x >> 1) * 4 + g;

  const int j4  = tid & 31;
  const int isl = tid >> 5;
  // cc split mapping: this CTA owns clusters [rank*8, rank*8+8)
  const int cL  = tid >> 6;          // local cluster 0..7
  const int hd  = (tid & 63) << 1;   // h-dim pair
  const int cG  = rank * 8 + cL;     // global cluster

  for (int i = tid; i < 4*16*132; i += 512) ((float*)S->sc)[i] = 0.f;
  if (tid < 64){ ((float*)S->ssp)[tid] = 1.f; ((float*)S->smaM)[tid] = 0.f; }
  __syncthreads();
  CLUSTER_SYNC();   // peer must not write into our sc before init completes

  unsigned peerScBase;
  asm("mapa.shared::cluster.u32 %0, %1, %2;" : "=r"(peerScBase)
      : "r"(s2u(S->sc)), "r"(rank ^ 1));

  for (int t = 0; t < 512; t++){
    const int tok = tokens[b*512 + t];
    const float valid = (tok != 0) ? 1.f : 0.f;
    if (ht == 0) S->sval[g] = valid;
    const float e = emb[tok*128 + ht];
    {
      float ps = rsum32(e);
      float pq = rsum32(e*e);
      if (lane == 0){ S->sred[g][wg][0] = ps; S->sred[g][wg][1] = pq; }
    }
    if (ht < 32){
      const bool ok = lane < 16;
      float sp = ok ? S->ssp[g][lane] : 0.f;
      float m  = ok ? S->smaM[g][lane] : 0.f;
      float score = ok ? m + logf(1.f/(sp+EPSF)+EPSF) : -3.4e38f;
      float mx = rmax16(score);
      float ex = ok ? expf(score - mx) : 0.f;
      float sm = rsum16(ex);
      float a  = ex / sm;
      if (ok) S->sal[g][lane] = a;
      float u   = rsum16(ok ? a*sp : 0.f);
      float ent = rsum16(ok ? -a*logf(fmaxf(a,1e-8f)) : 0.f);
      float mm2 = rmax16(ok ? m : -3.4e38f);
      float en  = mm2 + logf(rsum16(ok ? expf(m - mm2) : 0.f));
      if (lane == 0){ S->sciT[256][g] = u; S->sciT[258][g] = en; S->sciT[259][g] = ent; }
    }
    __syncthreads(); // S1
    {
      float mu = (S->sred[g][0][0]+S->sred[g][1][0]+S->sred[g][2][0]+S->sred[g][3][0]) * (1.f/128.f);
      float mq = (S->sred[g][0][1]+S->sred[g][1][1]+S->sred[g][2][1]+S->sred[g][3][1]) * (1.f/128.f);
      float var = mq - mu*mu;
      float te = (e - mu) * rsqrtf(var + 1e-5f) * ln_g[ht] + ln_b[ht];
      S->sciT[ht][g] = te;
      float core = 0.f;
      #pragma unroll
      for (int c = 0; c < 16; c++) core += S->sal[g][c] * S->sc[g][c][ht];
      S->sciT[128+ht][g] = core;
      float dv = 0.f;
      #pragma unroll
      for (int c = 0; c < 16; c++){ float dd = S->sc[g][c][ht] - core; dv += S->sal[g][c]*dd*dd; }
      dv = rsum32(dv);
      if (lane == 0) S->sred[g][wg][2] = dv;
    }
    __syncthreads(); // S2a
    if (ht == 0)
      S->sciT[257][g] = (S->sred[g][0][2]+S->sred[g][1][2]+S->sred[g][2][2]+S->sred[g][3][2]) * (1.f/128.f);
    __syncthreads(); // S2b

    // ---- w1 [260,128] ----
    {
      u64 aA[4] = {0,0,0,0}, aB[4] = {0,0,0,0};
      const int lo = isl * 16;
      #pragma unroll
      for (int r = 0; r < 16; r++){
        const int i = lo + r;
        ulonglong2 w = *(const ulonglong2*)&w1[i*128 + j4*4];
        float4 x = *(const float4*)&S->sciT[i][0];
        u64 p0=pack2(x.x), p1=pack2(x.y), p2=pack2(x.z), p3=pack2(x.w);
        fma2(aA[0], p0, w.x); fma2(aB[0], p0, w.y);
        fma2(aA[1], p1, w.x); fma2(aB[1], p1, w.y);
        fma2(aA[2], p2, w.x); fma2(aB[2], p2, w.y);
        fma2(aA[3], p3, w.x); fma2(aB[3], p3, w.y);
      }
      if (isl < 4){
        const int i = 256 + isl;
        ulonglong2 w = *(const ulonglong2*)&w1[i*128 + j4*4];
        float4 x = *(const float4*)&S->sciT[i][0];
        u64 p0=pack2(x.x), p1=pack2(x.y), p2=pack2(x.z), p3=pack2(x.w);
        fma2(aA[0], p0, w.x); fma2(aB[0], p0, w.y);
        fma2(aA[1], p1, w.x); fma2(aB[1], p1, w.y);
        fma2(aA[2], p2, w.x); fma2(aB[2], p2, w.y);
        fma2(aA[3], p3, w.x); fma2(aB[3], p3, w.y);
      }
      #pragma unroll
      for (int b2 = 0; b2 < 4; b2++){
        float2 l = unpack2(aA[b2]), h2 = unpack2(aB[b2]);
        *(float4*)&S->sbuf[isl][b2][j4*4] = make_float4(l.x, l.y, h2.x, h2.y);
      }
    }
    __syncthreads(); // S3
    {
      float s = b1[ht];
      #pragma unroll
      for (int k = 0; k < 16; k++) s += S->sbuf[k][g][ht];
      S->sh1T[ht][g] = tanhf(s);
    }
    __syncthreads(); // S4

    // ---- w2 [128,128] ----
    {
      u64 aA[4] = {0,0,0,0}, aB[4] = {0,0,0,0};
      const int lo = isl * 8;
      #pragma unroll
      for (int r = 0; r < 8; r++){
        const int i = lo + r;
        ulonglong2 w = *(const ulonglong2*)&w2[i*128 + j4*4];
        float4 x = *(const float4*)&S->sh1T[i][0];
        u64 p0=pack2(x.x), p1=pack2(x.y), p2=pack2(x.z), p3=pack2(x.w);
        fma2(aA[0], p0, w.x); fma2(aB[0], p0, w.y);
        fma2(aA[1], p1, w.x); fma2(aB[1], p1, w.y);
        fma2(aA[2], p2, w.x); fma2(aB[2], p2, w.y);
        fma2(aA[3], p3, w.x); fma2(aB[3], p3, w.y);
      }
      #pragma unroll
      for (int b2 = 0; b2 < 4; b2++){
        float2 l = unpack2(aA[b2]), h2 = unpack2(aB[b2]);
        *(float4*)&S->sbuf[isl][b2][j4*4] = make_float4(l.x, l.y, h2.x, h2.y);
      }
    }
    __syncthreads(); // S5
    {
      float s = b2[ht];
      #pragma unroll
      for (int k = 0; k < 16; k++) s += S->sbuf[k][g][ht];
      S->sct2[ht][g] = tanhf(s);
    }
    __syncthreads(); // S6

    // ---- cc_w: this CTA's half (clusters cG = rank*8 + 0..7), 8B loads ----
    u64 B0 = 0, B1 = 0, B2 = 0, B3 = 0;
    {
      const float* Wp = cc_w + cG*128 + hd;    // row i at + i*2048
      #pragma unroll 16
      for (int i = 0; i < 128; i++){
        u64 wp = *(const u64*)&Wp[i*2048];
        float4 ct = *(const float4*)&S->sct2[i][0];
        fma2(B0, pack2(ct.x), wp);
        fma2(B1, pack2(ct.y), wp);
        fma2(B2, pack2(ct.z), wp);
        fma2(B3, pack2(ct.w), wp);
      }
    }

    // ---- att_w [128,128] ----
    {
      u64 aA[4] = {0,0,0,0}, aB[4] = {0,0,0,0};
      const int lo = isl * 8;
      #pragma unroll
      for (int r = 0; r < 8; r++){
        const int i = lo + r;
        ulonglong2 w = *(const ulonglong2*)&att_w[i*128 + j4*4];
        float4 x = *(const float4*)&S->sct2[i][0];
        u64 p0=pack2(x.x), p1=pack2(x.y), p2=pack2(x.z), p3=pack2(x.w);
        fma2(aA[0], p0, w.x); fma2(aB[0], p0, w.y);
        fma2(aA[1], p1, w.x); fma2(aB[1], p1, w.y);
        fma2(aA[2], p2, w.x); fma2(aB[2], p2, w.y);
        fma2(aA[3], p3, w.x); fma2(aB[3], p3, w.y);
      }
      #pragma unroll
      for (int b2 = 0; b2 < 4; b2++){
        float2 l = unpack2(aA[b2]), h2 = unpack2(aB[b2]);
        *(float4*)&S->sbuf[isl][b2][j4*4] = make_float4(l.x, l.y, h2.x, h2.y);
      }
    }

    // ---- small heads + nov/relax ----
    if (ht < 64){
      const int head = ht >> 4;
      const int c = ht & 15;
      const float* W  = (head==0)? gate_w : (head==1)? assign_w : (head==2)? cs_w : md_w;
      const float* Bp = (head==0)? gate_b : (head==1)? assign_b : (head==2)? cs_b : md_b;
      float s = Bp[c];
      #pragma unroll 8
      for (int i = 0; i < 128; i++) s += S->sct2[i][g] * W[i*16 + c];
      S->sraw[g][head][c] = s;
    } else if (ht < 96){
      float s = 0.f;
      #pragma unroll
      for (int k = 0; k < 4; k++){ int i = (ht-64) + k*32; s += S->sct2[i][g] * nov_w[i]; }
      s = rsum32(s);
      if (lane == 0) S->snv[g] = sigm(s + nov_b[0]) * S->sval[g];
    } else {
      float s = 0.f;
      #pragma unroll
      for (int k = 0; k < 4; k++){ int i = (ht-96) + k*32; s += S->sct2[i][g] * relax_w[i]; }
      s = rsum32(s);
      if (lane == 0) S->srl[g] = sigm(s + relax_b[0]) * S->sval[g];
    }
    __syncthreads(); // S7
    {
      float s = att_b[ht];
      #pragma unroll
      for (int k = 0; k < 16; k++) s += S->sbuf[k][g][ht];
      S->satt[g][ht] = s;
    }
    if (ht < 32){
      const bool ok = lane < 16;
      float graw = ok ? S->sraw[g][0][lane] : 0.f;
      float araw = ok ? S->sraw[g][1][lane] : -3.4e38f;
      float mx = rmax16(araw);
      float ex = ok ? expf(araw - mx) : 0.f;
      float sm = rsum16(ex);
      if (ok){
        float assign = ex / sm;
        float gate = sigm(graw) * S->sval[g];
        float ss = gate * assign;
        S->sgs[g][lane] = ss;
        float cs = splus(S->sraw[g][2][lane]) + EPSF;
        float md = tanhf(S->sraw[g][3][lane]);
        float sp = S->ssp[g][lane]; sp += ss*(cs - sp); S->ssp[g][lane] = sp;
        float m  = S->smaM[g][lane]; m += ss*md;        S->smaM[g][lane] = m;
      }
    }
    __syncthreads(); // S8

    // ---- center update for own 8 clusters + DSMEM push to peer ----
    {
      float2 bv = *(const float2*)&cc_b[cG*128 + hd];
      const unsigned offBase = ((unsigned)cG*132u + (unsigned)hd) * 4u;
#define CUPD2(GG, BX) do{ \
      float2 l = unpack2(BX); \
      float cx = l.x + bv.x, cy = l.y + bv.y; \
      float ssv = S->sgs[GG][cG]; \
      float nv  = 0.1f * S->snv[GG]; \
      float ax = S->satt[GG][hd], ay = S->satt[GG][hd+1]; \
      float vx = S->sc[GG][cG][hd], vy = S->sc[GG][cG][hd+1]; \
      vx += ssv*(cx - vx); vx += nv*(ax - vx); \
      vy += ssv*(cy - vy); vy += nv*(ay - vy); \
      S->sc[GG][cG][hd] = vx; S->sc[GG][cG][hd+1] = vy; \
      u64 pk = packf2(vx, vy); \
      unsigned pa = peerScBase + ((GG)*16u*132u*4u) + offBase; \
      asm volatile("st.shared::cluster.u64 [%0], %1;" :: "r"(pa), "l"(pk) : "memory"); }while(0)
      CUPD2(0, B0);
      CUPD2(1, B1);
      CUPD2(2, B2);
      CUPD2(3, B3);
#undef CUPD2
    }
    CLUSTER_SYNC(); // S9: both halves of centers now present in both CTAs

    // ---- Gram ----
    {
      #pragma unroll
      for (int pp = 0; pp < 2; pp++){
        int p = ht + pp*128;
        int ii = p >> 4, jj = p & 15;
        const float4* Aa = (const float4*)S->sc[g][ii];
        const float4* Bv = (const float4*)S->sc[g][jj];
        float d0=0.f, d1=0.f, d2s=0.f, d3=0.f;
        #pragma unroll 8
        for (int k = 0; k < 32; k++){
          float4 a4 = Aa[k], b4 = Bv[k];
          d0 += a4.x*b4.x; d1 += a4.y*b4.y; d2s += a4.z*b4.z; d3 += a4.w*b4.w;
        }
        float dot = (d0+d1) + (d2s+d3);
        S->smix[g][ii][jj] = dot;
        if (ii == jj) S->ssq[g][ii] = dot;
      }
    }
    __syncthreads(); // S10
    {
      #pragma unroll
      for (int pass = 0; pass < 2; pass++){
        int row = pass*8 + wg*2 + (lane >> 4);
        int jj  = lane & 15;
        float Gij = S->smix[g][row][jj];
        float d2v = fmaxf(S->ssq[g][row] + S->ssq[g][jj] - 2.f*Gij, 0.f);
        float comp = -d2v / (S->ssp[g][row] + S->ssp[g][jj] + EPSF) + S->smaM[g][jj];
        float mx = rmax16(comp);
        float ex = expf(comp - mx);
        float sm = rsum16(ex);
        float mix = ex / sm;
        S->smix[g][row][jj] = mix;
        float msp = rsum16(mix * S->ssp[g][jj]);
        float mms = rsum16(mix * S->smaM[g][jj]);
        if ((lane & 15) == 0){ S->sms[g][row] = msp; S->smm[g][row] = mms; }
      }
    }
    __syncthreads(); // S11
    {
      float rl = S->srl[g];
      float cr[16];
      #pragma unroll
      for (int c = 0; c < 16; c++) cr[c] = S->sc[g][c][ht];
      #pragma unroll
      for (int i = 0; i < 16; i++){
        const float4* mr = (const float4*)S->smix[g][i];
        float4 m0 = mr[0], m1 = mr[1], m2v = mr[2], m3 = mr[3];
        float mc = m0.x*cr[0]+m0.y*cr[1]+m0.z*cr[2]+m0.w*cr[3]
                 + m1.x*cr[4]+m1.y*cr[5]+m1.z*cr[6]+m1.w*cr[7]
                 + m2v.x*cr[8]+m2v.y*cr[9]+m2v.z*cr[10]+m2v.w*cr[11]
                 + m3.x*cr[12]+m3.y*cr[13]+m3.z*cr[14]+m3.w*cr[15];
        S->sc[g][i][ht] = (1.f-rl)*cr[i] + rl*mc;
      }
      if (ht < 32){
        const bool ok = lane < 16;
        float rl2 = S->srl[g];
        float sp = ok ? S->ssp[g][lane] : 1.f;
        float m  = ok ? S->smaM[g][lane] : 0.f;
        float sp2 = (1.f-rl2)*sp + rl2*(ok ? S->sms[g][lane] : 0.f);
        float m2  = (1.f-rl2)*m  + rl2*(ok ? S->smm[g][lane] : 0.f);
        float score = ok ? m2 + logf(1.f/(sp2+EPSF)+EPSF) : -3.4e38f;
        float mx = rmax16(score);
        float ex = ok ? expf(score - mx) : 0.f;
        float sm = rsum16(ex);
        float ca = ex / sm;
        if (ok){ S->ssp[g][lane] = sp2*(1.f - 0.05f*ca*S->sval[g]) + EPSF; S->smaM[g][lane] = m2; }
      }
    }
    __syncthreads(); // S12
  }

  // ---- epilogue (both CTAs hold identical full state; both write same outputs) ----
  if (ht < 32){
    const bool ok = lane < 16;
    float sp = ok ? S->ssp[g][lane] : 0.f;
    float m  = ok ? S->smaM[g][lane] : 0.f;
    float score = ok ? m + logf(1.f/(sp+EPSF)+EPSF) : -3.4e38f;
    float mx = rmax16(score);
    float ex = ok ? expf(score - mx) : 0.f;
    float sm = rsum16(ex);
    float a  = ex / sm;
    if (ok) S->sal[g][lane] = a;
    float u   = rsum16(ok ? a*sp : 0.f);
    float ent = rsum16(ok ? -a*logf(fmaxf(a,1e-8f)) : 0.f);
    float mm2 = rmax16(ok ? m : -3.4e38f);
    float en  = mm2 + logf(rsum16(ok ? expf(m - mm2) : 0.f));
    float bv = ok ? a : -3.4e38f;
    int   bi = ok ? lane : 99;
    #pragma unroll
    for (int o = 8; o; o >>= 1){
      float ov = __shfl_xor_sync(0xffffffffu, bv, o);
      int   oi = __shfl_xor_sync(0xffffffffu, bi, o);
      if (ov > bv || (ov == bv && oi < bi)){ bv = ov; bi = oi; }
    }
    if (lane == 0){
      S->sciT[256][g] = u; S->sciT[258][g] = en; S->sciT[259][g] = ent; S->sidx[g] = bi;
    }
  }
  __syncthreads();
  {
    float core = 0.f;
    #pragma unroll
    for (int c = 0; c < 16; c++) core += S->sal[g][c] * S->sc[g][c][ht];
    float dv = 0.f;
    #pragma unroll
    for (int c = 0; c < 16; c++){ float dd = S->sc[g][c][ht] - core; dv += S->sal[g][c]*dd*dd; }
    dv = rsum32(dv);
    if (lane == 0) S->sred[g][wg][2] = dv;
    float strong = S->sc[g][S->sidx[g]][ht];
    S->sciT[ht][g] = core;
    S->sciT[128+ht][g] = strong;
  }
  __syncthreads();
  if (ht == 0)
    S->sciT[257][g] = (S->sred[g][0][2]+S->sred[g][1][2]+S->sred[g][2][2]+S->sred[g][3][2]) * (1.f/128.f);
  __syncthreads();
  {
    u64 aA[4] = {0,0,0,0}, aB[4] = {0,0,0,0};
    const int lo = isl * 16;
    #pragma unroll
    for (int r = 0; r < 16; r++){
      const int i = lo + r;
      ulonglong2 w = *(const ulonglong2*)&cw1[i*128 + j4*4];
      float4 x = *(const float4*)&S->sciT[i][0];
      u64 p0=pack2(x.x), p1=pack2(x.y), p2=pack2(x.z), p3=pack2(x.w);
      fma2(aA[0], p0, w.x); fma2(aB[0], p0, w.y);
      fma2(aA[1], p1, w.x); fma2(aB[1], p1, w.y);
      fma2(aA[2], p2, w.x); fma2(aB[2], p2, w.y);
      fma2(aA[3], p3, w.x); fma2(aB[3], p3, w.y);
    }
    if (isl < 4){
      const int i = 256 + isl;
      ulonglong2 w = *(const ulonglong2*)&cw1[i*128 + j4*4];
      float4 x = *(const float4*)&S->sciT[i][0];
      u64 p0=pack2(x.x), p1=pack2(x.y), p2=pack2(x.z), p3=pack2(x.w);
      fma2(aA[0], p0, w.x); fma2(aB[0], p0, w.y);
      fma2(aA[1], p1, w.x); fma2(aB[1], p1, w.y);
      fma2(aA[2], p2, w.x); fma2(aB[2], p2, w.y);
      fma2(aA[3], p3, w.x); fma2(aB[3], p3, w.y);
    }
    #pragma unroll
    for (int b2 = 0; b2 < 4; b2++){
      float2 l = unpack2(aA[b2]), h2 = unpack2(aB[b2]);
      *(float4*)&S->sbuf[isl][b2][j4*4] = make_float4(l.x, l.y, h2.x, h2.y);
    }
  }
  __syncthreads();
  {
    float s = cb1[ht];
    #pragma unroll
    for (int k = 0; k < 16; k++) s += S->sbuf[k][g][ht];
    S->sh1T[ht][g] = 0.5f * s * (1.f + erff(s * 0.70710678118654752440f));
  }
  __syncthreads();
  if (ht < 8 && rank == 0){
    float s = cb2[ht];
    #pragma unroll 4
    for (int i = 0; i < 128; i++) s += S->sh1T[i][g] * cw2[i*8 + ht];
    out[b*8 + ht] = s;
  }
  CLUSTER_SYNC(); // no CTA exits while peer DSMEM traffic could be in flight
}

extern "C" void kernel_launch(void* const* d_in, const int* in_sizes, int n_in,
                              void* d_out, int out_size){
  (void)in_sizes; (void)n_in; (void)out_size;
  cudaFuncSetAttribute(cfrm_kernel, cudaFuncAttributeMaxDynamicSharedMemorySize, (int)sizeof(Smem));
  cfrm_kernel<<<64, 512, sizeof(Smem)>>>(
    (const int*)  d_in[0],  (const float*)d_in[1],  (const float*)d_in[2],  (const float*)d_in[3],
    (const float*)d_in[4],  (const float*)d_in[5],  (const float*)d_in[6],  (const float*)d_in[7],
    (const float*)d_in[8],  (const float*)d_in[9],  (const float*)d_in[10], (const float*)d_in[11],
    (const float*)d_in[12], (const float*)d_in[13], (const float*)d_in[14], (const float*)d_in[15],
    (const float*)d_in[16], (const float*)d_in[17], (const float*)d_in[18], (const float*)d_in[19],
    (const float*)d_in[20], (const float*)d_in[21], (const float*)d_in[22], (const float*)d_in[23],
    (const float*)d_in[24], (const float*)d_in[25], (const float*)d_in[26], (const float*)d_in[27],
    (float*)d_out);
}

// round 12
// speedup vs baseline: 1.0367x; 1.0367x over previous
#include <cuda_runtime.h>
#include <math.h>

#define EPSF 1e-4f
typedef unsigned long long u64;

__device__ __forceinline__ u64 pack2(float x){
  u64 r; unsigned xi = __float_as_uint(x);
  asm("mov.b64 %0, {%1, %1};" : "=l"(r) : "r"(xi));
  return r;
}
__device__ __forceinline__ void fma2(u64 &acc, u64 a, u64 b){
  asm("fma.rn.f32x2 %0, %1, %2, %0;" : "+l"(acc) : "l"(a), "l"(b));
}
__device__ __forceinline__ float2 unpack2(u64 v){
  unsigned lo, hi;
  asm("mov.b64 {%0, %1}, %2;" : "=r"(lo), "=r"(hi) : "l"(v));
  return make_float2(__uint_as_float(lo), __uint_as_float(hi));
}
__device__ __forceinline__ float rsum32(float v){
  #pragma unroll
  for (int o=16;o;o>>=1) v += __shfl_xor_sync(0xffffffffu, v, o);
  return v;
}
__device__ __forceinline__ float rsum16(float v){
  #pragma unroll
  for (int o=8;o;o>>=1) v += __shfl_xor_sync(0xffffffffu, v, o);
  return v;
}
__device__ __forceinline__ float rmax16(float v){
  #pragma unroll
  for (int o=8;o;o>>=1) v = fmaxf(v, __shfl_xor_sync(0xffffffffu, v, o));
  return v;
}
__device__ __forceinline__ float sigm(float x){ return 1.f/(1.f+expf(-x)); }
__device__ __forceinline__ float splus(float x){ return fmaxf(x,0.f)+log1pf(expf(-fabsf(x))); }

struct Smem {
  float sciT[260][4];
  float sh1T[128][4];
  float sct2[128][4];
  float sc[4][16][132];
  float smix[4][16][16];
  float satt[4][128];
  float sbuf[16][4][128];
  float ssp[4][16], smaM[4][16], sal[4][16], sgs[4][16];
  float ssq[4][16], sms[4][16], smm[4][16];
  float sraw[4][4][16];
  float sred[4][4][3];
  float snv[4], srl[4], sval[4];
  int   sidx[4];
};

__global__ void __launch_bounds__(512,1) cfrm_kernel(
   const int* __restrict__ tokens, const float* __restrict__ emb,
   const float* __restrict__ ln_g, const float* __restrict__ ln_b,
   const float* __restrict__ w1, const float* __restrict__ b1,
   const float* __restrict__ w2, const float* __restrict__ b2,
   const float* __restrict__ gate_w, const float* __restrict__ gate_b,
   const float* __restrict__ assign_w, const float* __restrict__ assign_b,
   const float* __restrict__ nov_w, const float* __restrict__ nov_b,
   const float* __restrict__ relax_w, const float* __restrict__ relax_b,
   const float* __restrict__ cc_w, const float* __restrict__ cc_b,
   const float* __restrict__ cs_w, const float* __restrict__ cs_b,
   const float* __restrict__ md_w, const float* __restrict__ md_b,
   const float* __restrict__ att_w, const float* __restrict__ att_b,
   const float* __restrict__ cw1, const float* __restrict__ cb1,
   const float* __restrict__ cw2, const float* __restrict__ cb2,
   float* __restrict__ out)
{
  extern __shared__ __align__(128) char smem_raw[];
  Smem* S = (Smem*)smem_raw;

  const int tid  = threadIdx.x;
  const int g    = tid >> 7;
  const int ht   = tid & 127;
  const int lane = tid & 31;
  const int wg   = (tid >> 5) & 3;
  const int b    = blockIdx.x * 4 + g;

  const int j4  = tid & 31;
  const int isl = tid >> 5;

  for (int i = tid; i < 4*16*132; i += 512) ((float*)S->sc)[i] = 0.f;
  if (tid < 64){ ((float*)S->ssp)[tid] = 1.f; ((float*)S->smaM)[tid] = 0.f; }
  __syncthreads();

  for (int t = 0; t < 512; t++){
    const int tok = tokens[b*512 + t];
    const float valid = (tok != 0) ? 1.f : 0.f;
    if (ht == 0) S->sval[g] = valid;
    const float e = emb[tok*128 + ht];
    {
      float ps = rsum32(e);
      float pq = rsum32(e*e);
      if (lane == 0){ S->sred[g][wg][0] = ps; S->sred[g][wg][1] = pq; }
    }
    if (ht < 32){
      const bool ok = lane < 16;
      float sp = ok ? S->ssp[g][lane] : 0.f;
      float m  = ok ? S->smaM[g][lane] : 0.f;
      float score = ok ? m + logf(1.f/(sp+EPSF)+EPSF) : -3.4e38f;
      float mx = rmax16(score);
      float ex = ok ? expf(score - mx) : 0.f;
      float sm = rsum16(ex);
      float a  = ex / sm;
      if (ok) S->sal[g][lane] = a;
      float u   = rsum16(ok ? a*sp : 0.f);
      float ent = rsum16(ok ? -a*logf(fmaxf(a,1e-8f)) : 0.f);
      float mm2 = rmax16(ok ? m : -3.4e38f);
      float en  = mm2 + logf(rsum16(ok ? expf(m - mm2) : 0.f));
      if (lane == 0){ S->sciT[256][g] = u; S->sciT[258][g] = en; S->sciT[259][g] = ent; }
    }
    __syncthreads(); // S1
    {
      float mu = (S->sred[g][0][0]+S->sred[g][1][0]+S->sred[g][2][0]+S->sred[g][3][0]) * (1.f/128.f);
      float mq = (S->sred[g][0][1]+S->sred[g][1][1]+S->sred[g][2][1]+S->sred[g][3][1]) * (1.f/128.f);
      float var = mq - mu*mu;
      float te = (e - mu) * rsqrtf(var + 1e-5f) * ln_g[ht] + ln_b[ht];
      S->sciT[ht][g] = te;
      float core = 0.f;
      #pragma unroll
      for (int c = 0; c < 16; c++) core += S->sal[g][c] * S->sc[g][c][ht];
      S->sciT[128+ht][g] = core;
      float dv = 0.f;
      #pragma unroll
      for (int c = 0; c < 16; c++){ float dd = S->sc[g][c][ht] - core; dv += S->sal[g][c]*dd*dd; }
      dv = rsum32(dv);
      if (lane == 0) S->sred[g][wg][2] = dv;
    }
    __syncthreads(); // S2a
    if (ht == 0)
      S->sciT[257][g] = (S->sred[g][0][2]+S->sred[g][1][2]+S->sred[g][2][2]+S->sred[g][3][2]) * (1.f/128.f);
    __syncthreads(); // S2b

    // ---- w1 [260,128] ----
    {
      u64 aA[4] = {0,0,0,0}, aB[4] = {0,0,0,0};
      const int lo = isl * 16;
      #pragma unroll
      for (int r = 0; r < 16; r++){
        const int i = lo + r;
        ulonglong2 w = *(const ulonglong2*)&w1[i*128 + j4*4];
        float4 x = *(const float4*)&S->sciT[i][0];
        u64 p0=pack2(x.x), p1=pack2(x.y), p2=pack2(x.z), p3=pack2(x.w);
        fma2(aA[0], p0, w.x); fma2(aB[0], p0, w.y);
        fma2(aA[1], p1, w.x); fma2(aB[1], p1, w.y);
        fma2(aA[2], p2, w.x); fma2(aB[2], p2, w.y);
        fma2(aA[3], p3, w.x); fma2(aB[3], p3, w.y);
      }
      if (isl < 4){
        const int i = 256 + isl;
        ulonglong2 w = *(const ulonglong2*)&w1[i*128 + j4*4];
        float4 x = *(const float4*)&S->sciT[i][0];
        u64 p0=pack2(x.x), p1=pack2(x.y), p2=pack2(x.z), p3=pack2(x.w);
        fma2(aA[0], p0, w.x); fma2(aB[0], p0, w.y);
        fma2(aA[1], p1, w.x); fma2(aB[1], p1, w.y);
        fma2(aA[2], p2, w.x); fma2(aB[2], p2, w.y);
        fma2(aA[3], p3, w.x); fma2(aB[3], p3, w.y);
      }
      #pragma unroll
      for (int b2 = 0; b2 < 4; b2++){
        float2 l = unpack2(aA[b2]), h2 = unpack2(aB[b2]);
        *(float4*)&S->sbuf[isl][b2][j4*4] = make_float4(l.x, l.y, h2.x, h2.y);
      }
    }
    __syncthreads(); // S3
    {
      float s = b1[ht];
      #pragma unroll
      for (int k = 0; k < 16; k++) s += S->sbuf[k][g][ht];
      S->sh1T[ht][g] = tanhf(s);
    }
    __syncthreads(); // S4

    // ---- w2 [128,128] ----
    {
      u64 aA[4] = {0,0,0,0}, aB[4] = {0,0,0,0};
      const int lo = isl * 8;
      #pragma unroll
      for (int r = 0; r < 8; r++){
        const int i = lo + r;
        ulonglong2 w = *(const ulonglong2*)&w2[i*128 + j4*4];
        float4 x = *(const float4*)&S->sh1T[i][0];
        u64 p0=pack2(x.x), p1=pack2(x.y), p2=pack2(x.z), p3=pack2(x.w);
        fma2(aA[0], p0, w.x); fma2(aB[0], p0, w.y);
        fma2(aA[1], p1, w.x); fma2(aB[1], p1, w.y);
        fma2(aA[2], p2, w.x); fma2(aB[2], p2, w.y);
        fma2(aA[3], p3, w.x); fma2(aB[3], p3, w.y);
      }
      #pragma unroll
      for (int b2 = 0; b2 < 4; b2++){
        float2 l = unpack2(aA[b2]), h2 = unpack2(aB[b2]);
        *(float4*)&S->sbuf[isl][b2][j4*4] = make_float4(l.x, l.y, h2.x, h2.y);
      }
    }
    __syncthreads(); // S5
    {
      float s = b2[ht];
      #pragma unroll
      for (int k = 0; k < 16; k++) s += S->sbuf[k][g][ht];
      S->sct2[ht][g] = tanhf(s);
    }
    __syncthreads(); // S6

    // ---- small heads: cooperative 512-thread matvec (before cc so its
    //      single load latency overlaps the cc stream) ----
    {
      const int w16  = tid >> 5;           // 0..15
      const int head = w16 >> 2;           // 0..3
      const int c4o  = (w16 & 3) * 4;      // column group
      const float* W = (head==0)? gate_w : (head==1)? assign_w : (head==2)? cs_w : md_w;
      float4 a0 = {0,0,0,0}, a1 = {0,0,0,0}, a2 = {0,0,0,0}, a3 = {0,0,0,0};
      #pragma unroll
      for (int r = 0; r < 4; r++){
        const int i = lane*4 + r;
        float4 w4 = *(const float4*)&W[i*16 + c4o];
        float4 x4 = *(const float4*)&S->sct2[i][0];
        a0.x += x4.x*w4.x; a0.y += x4.x*w4.y; a0.z += x4.x*w4.z; a0.w += x4.x*w4.w;
        a1.x += x4.y*w4.x; a1.y += x4.y*w4.y; a1.z += x4.y*w4.z; a1.w += x4.y*w4.w;
        a2.x += x4.z*w4.x; a2.y += x4.z*w4.y; a2.z += x4.z*w4.z; a2.w += x4.z*w4.w;
        a3.x += x4.w*w4.x; a3.y += x4.w*w4.y; a3.z += x4.w*w4.z; a3.w += x4.w*w4.w;
      }
      #pragma unroll
      for (int o = 16; o; o >>= 1){
        a0.x += __shfl_xor_sync(0xffffffffu, a0.x, o);
        a0.y += __shfl_xor_sync(0xffffffffu, a0.y, o);
        a0.z += __shfl_xor_sync(0xffffffffu, a0.z, o);
        a0.w += __shfl_xor_sync(0xffffffffu, a0.w, o);
        a1.x += __shfl_xor_sync(0xffffffffu, a1.x, o);
        a1.y += __shfl_xor_sync(0xffffffffu, a1.y, o);
        a1.z += __shfl_xor_sync(0xffffffffu, a1.z, o);
        a1.w += __shfl_xor_sync(0xffffffffu, a1.w, o);
        a2.x += __shfl_xor_sync(0xffffffffu, a2.x, o);
        a2.y += __shfl_xor_sync(0xffffffffu, a2.y, o);
        a2.z += __shfl_xor_sync(0xffffffffu, a2.z, o);
        a2.w += __shfl_xor_sync(0xffffffffu, a2.w, o);
        a3.x += __shfl_xor_sync(0xffffffffu, a3.x, o);
        a3.y += __shfl_xor_sync(0xffffffffu, a3.y, o);
        a3.z += __shfl_xor_sync(0xffffffffu, a3.z, o);
        a3.w += __shfl_xor_sync(0xffffffffu, a3.w, o);
      }
      if (lane == 0){
        const float* Bp = (head==0)? gate_b : (head==1)? assign_b : (head==2)? cs_b : md_b;
        float b0 = Bp[c4o+0], b1v = Bp[c4o+1], b2v = Bp[c4o+2], b3v = Bp[c4o+3];
        S->sraw[0][head][c4o+0] = a0.x + b0; S->sraw[0][head][c4o+1] = a0.y + b1v;
        S->sraw[0][head][c4o+2] = a0.z + b2v; S->sraw[0][head][c4o+3] = a0.w + b3v;
        S->sraw[1][head][c4o+0] = a1.x + b0; S->sraw[1][head][c4o+1] = a1.y + b1v;
        S->sraw[1][head][c4o+2] = a1.z + b2v; S->sraw[1][head][c4o+3] = a1.w + b3v;
        S->sraw[2][head][c4o+0] = a2.x + b0; S->sraw[2][head][c4o+1] = a2.y + b1v;
        S->sraw[2][head][c4o+2] = a2.z + b2v; S->sraw[2][head][c4o+3] = a2.w + b3v;
        S->sraw[3][head][c4o+0] = a3.x + b0; S->sraw[3][head][c4o+1] = a3.y + b1v;
        S->sraw[3][head][c4o+2] = a3.z + b2v; S->sraw[3][head][c4o+3] = a3.w + b3v;
      }
    }
    // ---- nov/relax (8 warps, 4 LDG each) ----
    if (tid < 256){
      int w = tid >> 5; int g2 = w & 3; int rel = w >> 2;
      const float* vw = rel ? relax_w : nov_w;
      float s = 0.f;
      #pragma unroll
      for (int k = 0; k < 4; k++){ int i = lane + k*32; s += S->sct2[i][g2] * vw[i]; }
      s = rsum32(s);
      if (lane == 0){
        float r = sigm(s + (rel ? relax_b[0] : nov_b[0])) * S->sval[g2];
        if (rel) S->srl[g2] = r; else S->snv[g2] = r;
      }
    }

    // ---- cc_w [128,2048]: unroll 16 ----
    u64 A0[2] = {0,0}, A1[2] = {0,0}, A2[2] = {0,0}, A3[2] = {0,0};
    {
      const ulonglong2* W = (const ulonglong2*)cc_w;
      #pragma unroll 16
      for (int i = 0; i < 128; i++){
        ulonglong2 wv = W[i*512 + tid];
        float4 ct = *(const float4*)&S->sct2[i][0];
        u64 p0 = pack2(ct.x), p1 = pack2(ct.y), p2 = pack2(ct.z), p3 = pack2(ct.w);
        fma2(A0[0], p0, wv.x); fma2(A0[1], p0, wv.y);
        fma2(A1[0], p1, wv.x); fma2(A1[1], p1, wv.y);
        fma2(A2[0], p2, wv.x); fma2(A2[1], p2, wv.y);
        fma2(A3[0], p3, wv.x); fma2(A3[1], p3, wv.y);
      }
    }

    // ---- att_w [128,128] ----
    {
      u64 aA[4] = {0,0,0,0}, aB[4] = {0,0,0,0};
      const int lo = isl * 8;
      #pragma unroll
      for (int r = 0; r < 8; r++){
        const int i = lo + r;
        ulonglong2 w = *(const ulonglong2*)&att_w[i*128 + j4*4];
        float4 x = *(const float4*)&S->sct2[i][0];
        u64 p0=pack2(x.x), p1=pack2(x.y), p2=pack2(x.z), p3=pack2(x.w);
        fma2(aA[0], p0, w.x); fma2(aB[0], p0, w.y);
        fma2(aA[1], p1, w.x); fma2(aB[1], p1, w.y);
        fma2(aA[2], p2, w.x); fma2(aB[2], p2, w.y);
        fma2(aA[3], p3, w.x); fma2(aB[3], p3, w.y);
      }
      #pragma unroll
      for (int b2 = 0; b2 < 4; b2++){
        float2 l = unpack2(aA[b2]), h2 = unpack2(aB[b2]);
        *(float4*)&S->sbuf[isl][b2][j4*4] = make_float4(l.x, l.y, h2.x, h2.y);
      }
    }
    __syncthreads(); // S7
    {
      float s = att_b[ht];
      #pragma unroll
      for (int k = 0; k < 16; k++) s += S->sbuf[k][g][ht];
      S->satt[g][ht] = s;
    }
    if (ht < 32){
      const bool ok = lane < 16;
      float graw = ok ? S->sraw[g][0][lane] : 0.f;
      float araw = ok ? S->sraw[g][1][lane] : -3.4e38f;
      float mx = rmax16(araw);
      float ex = ok ? expf(araw - mx) : 0.f;
      float sm = rsum16(ex);
      if (ok){
        float assign = ex / sm;
        float gate = sigm(graw) * S->sval[g];
        float ss = gate * assign;
        S->sgs[g][lane] = ss;
        float cs = splus(S->sraw[g][2][lane]) + EPSF;
        float md = tanhf(S->sraw[g][3][lane]);
        float sp = S->ssp[g][lane]; sp += ss*(cs - sp); S->ssp[g][lane] = sp;
        float m  = S->smaM[g][lane]; m += ss*md;        S->smaM[g][lane] = m;
      }
    }
    __syncthreads(); // S8

    // ---- center update ----
    {
      const int ccC = tid >> 5, ccH = tid & 31;
      float4 bv = *(const float4*)&cc_b[ccC*128 + ccH*4];
      float4 at0 = *(const float4*)&S->satt[0][ccH*4];
      float4 at1 = *(const float4*)&S->satt[1][ccH*4];
      float4 at2 = *(const float4*)&S->satt[2][ccH*4];
      float4 at3 = *(const float4*)&S->satt[3][ccH*4];
#define CUPD(GG, AX, AT) do{ \
      float2 l  = unpack2(AX[0]); \
      float2 hh = unpack2(AX[1]); \
      float4 cand = make_float4(l.x+bv.x, l.y+bv.y, hh.x+bv.z, hh.y+bv.w); \
      float ssv = S->sgs[GG][ccC]; \
      float nv  = 0.1f * S->snv[GG]; \
      float4 v  = *(float4*)&S->sc[GG][ccC][ccH*4]; \
      v.x += ssv*(cand.x - v.x); v.x += nv*(AT.x - v.x); \
      v.y += ssv*(cand.y - v.y); v.y += nv*(AT.y - v.y); \
      v.z += ssv*(cand.z - v.z); v.z += nv*(AT.z - v.z); \
      v.w += ssv*(cand.w - v.w); v.w += nv*(AT.w - v.w); \
      *(float4*)&S->sc[GG][ccC][ccH*4] = v; }while(0)
      CUPD(0, A0, at0);
      CUPD(1, A1, at1);
      CUPD(2, A2, at2);
      CUPD(3, A3, at3);
#undef CUPD
    }
    __syncthreads(); // S9

    // ---- Gram ----
    {
      #pragma unroll
      for (int pp = 0; pp < 2; pp++){
        int p = ht + pp*128;
        int ii = p >> 4, jj = p & 15;
        const float4* Aa = (const float4*)S->sc[g][ii];
        const float4* Bv = (const float4*)S->sc[g][jj];
        float d0=0.f, d1=0.f, d2s=0.f, d3=0.f;
        #pragma unroll 8
        for (int k = 0; k < 32; k++){
          float4 a4 = Aa[k], b4 = Bv[k];
          d0 += a4.x*b4.x; d1 += a4.y*b4.y; d2s += a4.z*b4.z; d3 += a4.w*b4.w;
        }
        float dot = (d0+d1) + (d2s+d3);
        S->smix[g][ii][jj] = dot;
        if (ii == jj) S->ssq[g][ii] = dot;
      }
    }
    __syncthreads(); // S10
    {
      #pragma unroll
      for (int pass = 0; pass < 2; pass++){
        int row = pass*8 + wg*2 + (lane >> 4);
        int jj  = lane & 15;
        float Gij = S->smix[g][row][jj];
        float d2v = fmaxf(S->ssq[g][row] + S->ssq[g][jj] - 2.f*Gij, 0.f);
        float comp = -d2v / (S->ssp[g][row] + S->ssp[g][jj] + EPSF) + S->smaM[g][jj];
        float mx = rmax16(comp);
        float ex = expf(comp - mx);
        float sm = rsum16(ex);
        float mix = ex / sm;
        S->smix[g][row][jj] = mix;
        float msp = rsum16(mix * S->ssp[g][jj]);
        float mms = rsum16(mix * S->smaM[g][jj]);
        if ((lane & 15) == 0){ S->sms[g][row] = msp; S->smm[g][row] = mms; }
      }
    }
    __syncthreads(); // S11
    {
      float rl = S->srl[g];
      float cr[16];
      #pragma unroll
      for (int c = 0; c < 16; c++) cr[c] = S->sc[g][c][ht];
      #pragma unroll
      for (int i = 0; i < 16; i++){
        const float4* mr = (const float4*)S->smix[g][i];
        float4 m0 = mr[0], m1 = mr[1], m2v = mr[2], m3 = mr[3];
        float mc = m0.x*cr[0]+m0.y*cr[1]+m0.z*cr[2]+m0.w*cr[3]
                 + m1.x*cr[4]+m1.y*cr[5]+m1.z*cr[6]+m1.w*cr[7]
                 + m2v.x*cr[8]+m2v.y*cr[9]+m2v.z*cr[10]+m2v.w*cr[11]
                 + m3.x*cr[12]+m3.y*cr[13]+m3.z*cr[14]+m3.w*cr[15];
        S->sc[g][i][ht] = (1.f-rl)*cr[i] + rl*mc;
      }
      if (ht < 32){
        const bool ok = lane < 16;
        float rl2 = S->srl[g];
        float sp = ok ? S->ssp[g][lane] : 1.f;
        float m  = ok ? S->smaM[g][lane] : 0.f;
        float sp2 = (1.f-rl2)*sp + rl2*(ok ? S->sms[g][lane] : 0.f);
        float m2  = (1.f-rl2)*m  + rl2*(ok ? S->smm[g][lane] : 0.f);
        float score = ok ? m2 + logf(1.f/(sp2+EPSF)+EPSF) : -3.4e38f;
        float mx = rmax16(score);
        float ex = ok ? expf(score - mx) : 0.f;
        float sm = rsum16(ex);
        float ca = ex / sm;
        if (ok){ S->ssp[g][lane] = sp2*(1.f - 0.05f*ca*S->sval[g]) + EPSF; S->smaM[g][lane] = m2; }
      }
    }
    __syncthreads(); // S12
  }

  // ---- epilogue ----
  if (ht < 32){
    const bool ok = lane < 16;
    float sp = ok ? S->ssp[g][lane] : 0.f;
    float m  = ok ? S->smaM[g][lane] : 0.f;
    float score = ok ? m + logf(1.f/(sp+EPSF)+EPSF) : -3.4e38f;
    float mx = rmax16(score);
    float ex = ok ? expf(score - mx) : 0.f;
    float sm = rsum16(ex);
    float a  = ex / sm;
    if (ok) S->sal[g][lane] = a;
    float u   = rsum16(ok ? a*sp : 0.f);
    float ent = rsum16(ok ? -a*logf(fmaxf(a,1e-8f)) : 0.f);
    float mm2 = rmax16(ok ? m : -3.4e38f);
    float en  = mm2 + logf(rsum16(ok ? expf(m - mm2) : 0.f));
    float bv = ok ? a : -3.4e38f;
    int   bi = ok ? lane : 99;
    #pragma unroll
    for (int o = 8; o; o >>= 1){
      float ov = __shfl_xor_sync(0xffffffffu, bv, o);
      int   oi = __shfl_xor_sync(0xffffffffu, bi, o);
      if (ov > bv || (ov == bv && oi < bi)){ bv = ov; bi = oi; }
    }
    if (lane == 0){
      S->sciT[256][g] = u; S->sciT[258][g] = en; S->sciT[259][g] = ent; S->sidx[g] = bi;
    }
  }
  __syncthreads();
  {
    float core = 0.f;
    #pragma unroll
    for (int c = 0; c < 16; c++) core += S->sal[g][c] * S->sc[g][c][ht];
    float dv = 0.f;
    #pragma unroll
    for (int c = 0; c < 16; c++){ float dd = S->sc[g][c][ht] - core; dv += S->sal[g][c]*dd*dd; }
    dv = rsum32(dv);
    if (lane == 0) S->sred[g][wg][2] = dv;
    float strong = S->sc[g][S->sidx[g]][ht];
    S->sciT[ht][g] = core;
    S->sciT[128+ht][g] = strong;
  }
  __syncthreads();
  if (ht == 0)
    S->sciT[257][g] = (S->sred[g][0][2]+S->sred[g][1][2]+S->sred[g][2][2]+S->sred[g][3][2]) * (1.f/128.f);
  __syncthreads();
  {
    u64 aA[4] = {0,0,0,0}, aB[4] = {0,0,0,0};
    const int lo = isl * 16;
    #pragma unroll
    for (int r = 0; r < 16; r++){
      const int i = lo + r;
      ulonglong2 w = *(const ulonglong2*)&cw1[i*128 + j4*4];
      float4 x = *(const float4*)&S->sciT[i][0];
      u64 p0=pack2(x.x), p1=pack2(x.y), p2=pack2(x.z), p3=pack2(x.w);
      fma2(aA[0], p0, w.x); fma2(aB[0], p0, w.y);
      fma2(aA[1], p1, w.x); fma2(aB[1], p1, w.y);
      fma2(aA[2], p2, w.x); fma2(aB[2], p2, w.y);
      fma2(aA[3], p3, w.x); fma2(aB[3], p3, w.y);
    }
    if (isl < 4){
      const int i = 256 + isl;
      ulonglong2 w = *(const ulonglong2*)&cw1[i*128 + j4*4];
      float4 x = *(const float4*)&S->sciT[i][0];
      u64 p0=pack2(x.x), p1=pack2(x.y), p2=pack2(x.z), p3=pack2(x.w);
      fma2(aA[0], p0, w.x); fma2(aB[0], p0, w.y);
      fma2(aA[1], p1, w.x); fma2(aB[1], p1, w.y);
      fma2(aA[2], p2, w.x); fma2(aB[2], p2, w.y);
      fma2(aA[3], p3, w.x); fma2(aB[3], p3, w.y);
    }
    #pragma unroll
    for (int b2 = 0; b2 < 4; b2++){
      float2 l = unpack2(aA[b2]), h2 = unpack2(aB[b2]);
      *(float4*)&S->sbuf[isl][b2][j4*4] = make_float4(l.x, l.y, h2.x, h2.y);
    }
  }
  __syncthreads();
  {
    float s = cb1[ht];
    #pragma unroll
    for (int k = 0; k < 16; k++) s += S->sbuf[k][g][ht];
    S->sh1T[ht][g] = 0.5f * s * (1.f + erff(s * 0.70710678118654752440f));
  }
  __syncthreads();
  if (ht < 8){
    float s = cb2[ht];
    #pragma unroll 4
    for (int i = 0; i < 128; i++) s += S->sh1T[i][g] * cw2[i*8 + ht];
    out[b*8 + ht] = s;
  }
}

extern "C" void kernel_launch(void* const* d_in, const int* in_sizes, int n_in,
                              void* d_out, int out_size){
  (void)in_sizes; (void)n_in; (void)out_size;
  cudaFuncSetAttribute(cfrm_kernel, cudaFuncAttributeMaxDynamicSharedMemorySize, (int)sizeof(Smem));
  cfrm_kernel<<<32, 512, sizeof(Smem)>>>(
    (const int*)  d_in[0],  (const float*)d_in[1],  (const float*)d_in[2],  (const float*)d_in[3],
    (const float*)d_in[4],  (const float*)d_in[5],  (const float*)d_in[6],  (const float*)d_in[7],
    (const float*)d_in[8],  (const float*)d_in[9],  (const float*)d_in[10], (const float*)d_in[11],
    (const float*)d_in[12], (const float*)d_in[13], (const float*)d_in[14], (const float*)d_in[15],
    (const float*)d_in[16], (const float*)d_in[17], (const float*)d_in[18], (const float*)d_in[19],
    (const float*)d_in[20], (const float*)d_in[21], (const float*)d_in[22], (const float*)d_in[23],
    (const float*)d_in[24], (const float*)d_in[25], (const float*)d_in[26], (const float*)d_in[27],
    (float*)d_out);
}

// round 13
// speedup vs baseline: 1.5365x; 1.4821x over previous
#include <cuda_runtime.h>
#include <math.h>

#define EPSF 1e-4f
typedef unsigned long long u64;

__device__ __forceinline__ u64 pack2(float x){
  u64 r; unsigned xi = __float_as_uint(x);
  asm("mov.b64 %0, {%1, %1};" : "=l"(r) : "r"(xi));
  return r;
}
__device__ __forceinline__ void fma2(u64 &acc, u64 a, u64 b){
  asm("fma.rn.f32x2 %0, %1, %2, %0;" : "+l"(acc) : "l"(a), "l"(b));
}
__device__ __forceinline__ float2 unpack2(u64 v){
  unsigned lo, hi;
  asm("mov.b64 {%0, %1}, %2;" : "=r"(lo), "=r"(hi) : "l"(v));
  return make_float2(__uint_as_float(lo), __uint_as_float(hi));
}
__device__ __forceinline__ float rsum32(float v){
  #pragma unroll
  for (int o=16;o;o>>=1) v += __shfl_xor_sync(0xffffffffu, v, o);
  return v;
}
__device__ __forceinline__ float rsum16(float v){
  #pragma unroll
  for (int o=8;o;o>>=1) v += __shfl_xor_sync(0xffffffffu, v, o);
  return v;
}
__device__ __forceinline__ float rmax16(float v){
  #pragma unroll
  for (int o=8;o;o>>=1) v = fmaxf(v, __shfl_xor_sync(0xffffffffu, v, o));
  return v;
}
__device__ __forceinline__ float sigm(float x){ return 1.f/(1.f+expf(-x)); }
__device__ __forceinline__ float splus(float x){ return fmaxf(x,0.f)+log1pf(expf(-fabsf(x))); }

struct Smem {
  float sciT[260][2];
  float sh1T[128][2];
  float sct2[128][2];
  float sc[2][16][132];
  float smix[2][16][16];
  float satt[2][128];
  float sbuf[16][2][128];
  float ssp[2][16], smaM[2][16], sal[2][16], sgs[2][16];
  float ssq[2][16], sms[2][16], smm[2][16];
  float sraw[2][4][16];
  float sred[2][4][3];
  float snv[2], srl[2], sval[2];
  int   sidx[2];
};

__global__ void __launch_bounds__(512,1) cfrm_kernel(
   const int* __restrict__ tokens, const float* __restrict__ emb,
   const float* __restrict__ ln_g, const float* __restrict__ ln_b,
   const float* __restrict__ w1, const float* __restrict__ b1,
   const float* __restrict__ w2, const float* __restrict__ b2,
   const float* __restrict__ gate_w, const float* __restrict__ gate_b,
   const float* __restrict__ assign_w, const float* __restrict__ assign_b,
   const float* __restrict__ nov_w, const float* __restrict__ nov_b,
   const float* __restrict__ relax_w, const float* __restrict__ relax_b,
   const float* __restrict__ cc_w, const float* __restrict__ cc_b,
   const float* __restrict__ cs_w, const float* __restrict__ cs_b,
   const float* __restrict__ md_w, const float* __restrict__ md_b,
   const float* __restrict__ att_w, const float* __restrict__ att_b,
   const float* __restrict__ cw1, const float* __restrict__ cb1,
   const float* __restrict__ cw2, const float* __restrict__ cb2,
   float* __restrict__ out)
{
  extern __shared__ __align__(128) char smem_raw[];
  Smem* S = (Smem*)smem_raw;

  const int tid  = threadIdx.x;
  const int g    = tid >> 7;        // 0..3; batches are g<2
  const int ht   = tid & 127;
  const int lane = tid & 31;
  const int wg   = (tid >> 5) & 3;
  const int b    = blockIdx.x * 2 + (g & 1);

  const int j4  = tid & 31;
  const int isl = tid >> 5;

  for (int i = tid; i < 2*16*132; i += 512) ((float*)S->sc)[i] = 0.f;
  if (tid < 32){ ((float*)S->ssp)[tid] = 1.f; ((float*)S->smaM)[tid] = 0.f; }
  __syncthreads();

  for (int t = 0; t < 512; t++){
    if (g < 2){
      const int tok = tokens[b*512 + t];
      const float valid = (tok != 0) ? 1.f : 0.f;
      if (ht == 0) S->sval[g] = valid;
      const float e = emb[tok*128 + ht];
      float ps = rsum32(e);
      float pq = rsum32(e*e);
      if (lane == 0){ S->sred[g][wg][0] = ps; S->sred[g][wg][1] = pq; }
      // stash e for LN after the barrier via register (recompute-free path):
      // store raw e into sciT temporarily
      S->sciT[ht][g] = e;
    }
    if (g == 2 && ht < 32){
      const int gb = lane >> 4;      // summarize both batches on warp 8
      const int c  = lane & 15;
      float sp = S->ssp[gb][c];
      float m  = S->smaM[gb][c];
      float score = m + logf(1.f/(sp+EPSF)+EPSF);
      float mx = rmax16(score);
      float ex = expf(score - mx);
      float sm = rsum16(ex);
      float a  = ex / sm;
      S->sal[gb][c] = a;
      float u   = rsum16(a*sp);
      float ent = rsum16(-a*logf(fmaxf(a,1e-8f)));
      float mm2 = rmax16(m);
      float en  = mm2 + logf(rsum16(expf(m - mm2)));
      if (c == 0){ S->sciT[256][gb] = u; S->sciT[258][gb] = en; S->sciT[259][gb] = ent; }
    }
    __syncthreads(); // S1
    if (g < 2){
      const float e = S->sciT[ht][g];
      float mu = (S->sred[g][0][0]+S->sred[g][1][0]+S->sred[g][2][0]+S->sred[g][3][0]) * (1.f/128.f);
      float mq = (S->sred[g][0][1]+S->sred[g][1][1]+S->sred[g][2][1]+S->sred[g][3][1]) * (1.f/128.f);
      float var = mq - mu*mu;
      float te = (e - mu) * rsqrtf(var + 1e-5f) * ln_g[ht] + ln_b[ht];
      S->sciT[ht][g] = te;
      float core = 0.f;
      #pragma unroll
      for (int c = 0; c < 16; c++) core += S->sal[g][c] * S->sc[g][c][ht];
      S->sciT[128+ht][g] = core;
      float dv = 0.f;
      #pragma unroll
      for (int c = 0; c < 16; c++){ float dd = S->sc[g][c][ht] - core; dv += S->sal[g][c]*dd*dd; }
      dv = rsum32(dv);
      if (lane == 0) S->sred[g][wg][2] = dv;
    }
    __syncthreads(); // S2a
    if (tid < 2)
      S->sciT[257][tid] = (S->sred[tid][0][2]+S->sred[tid][1][2]+S->sred[tid][2][2]+S->sred[tid][3][2]) * (1.f/128.f);
    __syncthreads(); // S2b

    // ---- w1 [260,128]: 16 slices x 32 float4 chunks, 2-batch accumulators ----
    {
      u64 ax[2] = {0,0}, ay[2] = {0,0};
      const int lo = isl * 16;
      #pragma unroll
      for (int r = 0; r < 16; r++){
        const int i = lo + r;
        ulonglong2 w = *(const ulonglong2*)&w1[i*128 + j4*4];
        float2 x = *(const float2*)&S->sciT[i][0];
        u64 p0 = pack2(x.x), p1 = pack2(x.y);
        fma2(ax[0], p0, w.x); fma2(ay[0], p0, w.y);
        fma2(ax[1], p1, w.x); fma2(ay[1], p1, w.y);
      }
      if (isl < 4){
        const int i = 256 + isl;
        ulonglong2 w = *(const ulonglong2*)&w1[i*128 + j4*4];
        float2 x = *(const float2*)&S->sciT[i][0];
        u64 p0 = pack2(x.x), p1 = pack2(x.y);
        fma2(ax[0], p0, w.x); fma2(ay[0], p0, w.y);
        fma2(ax[1], p1, w.x); fma2(ay[1], p1, w.y);
      }
      #pragma unroll
      for (int b2 = 0; b2 < 2; b2++){
        float2 l = unpack2(ax[b2]), h2 = unpack2(ay[b2]);
        *(float4*)&S->sbuf[isl][b2][j4*4] = make_float4(l.x, l.y, h2.x, h2.y);
      }
    }
    __syncthreads(); // S3
    if (g < 2){
      float s = b1[ht];
      #pragma unroll
      for (int k = 0; k < 16; k++) s += S->sbuf[k][g][ht];
      S->sh1T[ht][g] = tanhf(s);
    }
    __syncthreads(); // S4

    // ---- w2 [128,128] ----
    {
      u64 ax[2] = {0,0}, ay[2] = {0,0};
      const int lo = isl * 8;
      #pragma unroll
      for (int r = 0; r < 8; r++){
        const int i = lo + r;
        ulonglong2 w = *(const ulonglong2*)&w2[i*128 + j4*4];
        float2 x = *(const float2*)&S->sh1T[i][0];
        u64 p0 = pack2(x.x), p1 = pack2(x.y);
        fma2(ax[0], p0, w.x); fma2(ay[0], p0, w.y);
        fma2(ax[1], p1, w.x); fma2(ay[1], p1, w.y);
      }
      #pragma unroll
      for (int b2 = 0; b2 < 2; b2++){
        float2 l = unpack2(ax[b2]), h2 = unpack2(ay[b2]);
        *(float4*)&S->sbuf[isl][b2][j4*4] = make_float4(l.x, l.y, h2.x, h2.y);
      }
    }
    __syncthreads(); // S5
    if (g < 2){
      float s = b2[ht];
      #pragma unroll
      for (int k = 0; k < 16; k++) s += S->sbuf[k][g][ht];
      S->sct2[ht][g] = tanhf(s);
    }
    __syncthreads(); // S6

    // ---- small heads: cooperative 512-thread matvec ----
    {
      const int w16  = tid >> 5;
      const int head = w16 >> 2;
      const int c4o  = (w16 & 3) * 4;
      const float* W = (head==0)? gate_w : (head==1)? assign_w : (head==2)? cs_w : md_w;
      float4 a0 = {0,0,0,0}, a1 = {0,0,0,0};
      #pragma unroll
      for (int r = 0; r < 4; r++){
        const int i = lane*4 + r;
        float4 w4 = *(const float4*)&W[i*16 + c4o];
        float2 x2 = *(const float2*)&S->sct2[i][0];
        a0.x += x2.x*w4.x; a0.y += x2.x*w4.y; a0.z += x2.x*w4.z; a0.w += x2.x*w4.w;
        a1.x += x2.y*w4.x; a1.y += x2.y*w4.y; a1.z += x2.y*w4.z; a1.w += x2.y*w4.w;
      }
      #pragma unroll
      for (int o = 16; o; o >>= 1){
        a0.x += __shfl_xor_sync(0xffffffffu, a0.x, o);
        a0.y += __shfl_xor_sync(0xffffffffu, a0.y, o);
        a0.z += __shfl_xor_sync(0xffffffffu, a0.z, o);
        a0.w += __shfl_xor_sync(0xffffffffu, a0.w, o);
        a1.x += __shfl_xor_sync(0xffffffffu, a1.x, o);
        a1.y += __shfl_xor_sync(0xffffffffu, a1.y, o);
        a1.z += __shfl_xor_sync(0xffffffffu, a1.z, o);
        a1.w += __shfl_xor_sync(0xffffffffu, a1.w, o);
      }
      if (lane == 0){
        const float* Bp = (head==0)? gate_b : (head==1)? assign_b : (head==2)? cs_b : md_b;
        float b0 = Bp[c4o+0], b1v = Bp[c4o+1], b2v = Bp[c4o+2], b3v = Bp[c4o+3];
        S->sraw[0][head][c4o+0] = a0.x + b0;  S->sraw[0][head][c4o+1] = a0.y + b1v;
        S->sraw[0][head][c4o+2] = a0.z + b2v; S->sraw[0][head][c4o+3] = a0.w + b3v;
        S->sraw[1][head][c4o+0] = a1.x + b0;  S->sraw[1][head][c4o+1] = a1.y + b1v;
        S->sraw[1][head][c4o+2] = a1.z + b2v; S->sraw[1][head][c4o+3] = a1.w + b3v;
      }
    }
    // ---- nov/relax (4 warps) ----
    if (tid < 128){
      int w = tid >> 5; int g2 = w & 1; int rel = w >> 1;
      const float* vw = rel ? relax_w : nov_w;
      float s = 0.f;
      #pragma unroll
      for (int k = 0; k < 4; k++){ int i = lane + k*32; s += S->sct2[i][g2] * vw[i]; }
      s = rsum32(s);
      if (lane == 0){
        float r = sigm(s + (rel ? relax_b[0] : nov_b[0])) * S->sval[g2];
        if (rel) S->srl[g2] = r; else S->snv[g2] = r;
      }
    }

    // ---- cc_w [128,2048]: unroll 16, 2-batch accumulators ----
    u64 A0[2] = {0,0}, A1[2] = {0,0};
    {
      const ulonglong2* W = (const ulonglong2*)cc_w;
      #pragma unroll 16
      for (int i = 0; i < 128; i++){
        ulonglong2 wv = W[i*512 + tid];
        float2 ct = *(const float2*)&S->sct2[i][0];
        u64 p0 = pack2(ct.x), p1 = pack2(ct.y);
        fma2(A0[0], p0, wv.x); fma2(A0[1], p0, wv.y);
        fma2(A1[0], p1, wv.x); fma2(A1[1], p1, wv.y);
      }
    }

    // ---- att_w [128,128] ----
    {
      u64 ax[2] = {0,0}, ay[2] = {0,0};
      const int lo = isl * 8;
      #pragma unroll
      for (int r = 0; r < 8; r++){
        const int i = lo + r;
        ulonglong2 w = *(const ulonglong2*)&att_w[i*128 + j4*4];
        float2 x = *(const float2*)&S->sct2[i][0];
        u64 p0 = pack2(x.x), p1 = pack2(x.y);
        fma2(ax[0], p0, w.x); fma2(ay[0], p0, w.y);
        fma2(ax[1], p1, w.x); fma2(ay[1], p1, w.y);
      }
      #pragma unroll
      for (int b2 = 0; b2 < 2; b2++){
        float2 l = unpack2(ax[b2]), h2 = unpack2(ay[b2]);
        *(float4*)&S->sbuf[isl][b2][j4*4] = make_float4(l.x, l.y, h2.x, h2.y);
      }
    }
    __syncthreads(); // S7
    if (g < 2){
      float s = att_b[ht];
      #pragma unroll
      for (int k = 0; k < 16; k++) s += S->sbuf[k][g][ht];
      S->satt[g][ht] = s;
    }
    if (g == 2 && ht < 32){
      const int gb = lane >> 4;
      const int c  = lane & 15;
      float graw = S->sraw[gb][0][c];
      float araw = S->sraw[gb][1][c];
      float mx = rmax16(araw);
      float ex = expf(araw - mx);
      float sm = rsum16(ex);
      float assign = ex / sm;
      float gate = sigm(graw) * S->sval[gb];
      float ss = gate * assign;
      S->sgs[gb][c] = ss;
      float cs = splus(S->sraw[gb][2][c]) + EPSF;
      float md = tanhf(S->sraw[gb][3][c]);
      float sp = S->ssp[gb][c]; sp += ss*(cs - sp); S->ssp[gb][c] = sp;
      float m  = S->smaM[gb][c]; m += ss*md;        S->smaM[gb][c] = m;
    }
    __syncthreads(); // S8

    // ---- center update ----
    {
      const int ccC = tid >> 5, ccH = tid & 31;
      float4 bv = *(const float4*)&cc_b[ccC*128 + ccH*4];
      float4 at0 = *(const float4*)&S->satt[0][ccH*4];
      float4 at1 = *(const float4*)&S->satt[1][ccH*4];
#define CUPD(GG, AX, AT) do{ \
      float2 l  = unpack2(AX[0]); \
      float2 hh = unpack2(AX[1]); \
      float4 cand = make_float4(l.x+bv.x, l.y+bv.y, hh.x+bv.z, hh.y+bv.w); \
      float ssv = S->sgs[GG][ccC]; \
      float nv  = 0.1f * S->snv[GG]; \
      float4 v  = *(float4*)&S->sc[GG][ccC][ccH*4]; \
      v.x += ssv*(cand.x - v.x); v.x += nv*(AT.x - v.x); \
      v.y += ssv*(cand.y - v.y); v.y += nv*(AT.y - v.y); \
      v.z += ssv*(cand.z - v.z); v.z += nv*(AT.z - v.z); \
      v.w += ssv*(cand.w - v.w); v.w += nv*(AT.w - v.w); \
      *(float4*)&S->sc[GG][ccC][ccH*4] = v; }while(0)
      CUPD(0, A0, at0);
      CUPD(1, A1, at1);
#undef CUPD
    }
    __syncthreads(); // S9

    // ---- Gram: 1 pair per thread across 2 batches ----
    {
      const int gb = tid >> 8;
      const int p  = tid & 255;
      const int ii = p >> 4, jj = p & 15;
      const float4* Aa = (const float4*)S->sc[gb][ii];
      const float4* Bv = (const float4*)S->sc[gb][jj];
      float d0=0.f, d1=0.f, d2s=0.f, d3=0.f;
      #pragma unroll 8
      for (int k = 0; k < 32; k++){
        float4 a4 = Aa[k], b4 = Bv[k];
        d0 += a4.x*b4.x; d1 += a4.y*b4.y; d2s += a4.z*b4.z; d3 += a4.w*b4.w;
      }
      float dot = (d0+d1) + (d2s+d3);
      S->smix[gb][ii][jj] = dot;
      if (ii == jj) S->ssq[gb][ii] = dot;
    }
    __syncthreads(); // S10
    {
      const int gb  = tid >> 8;
      const int row = ((tid>>5)&7)*2 + (lane >> 4);
      const int jj  = lane & 15;
      float Gij = S->smix[gb][row][jj];
      float d2v = fmaxf(S->ssq[gb][row] + S->ssq[gb][jj] - 2.f*Gij, 0.f);
      float comp = -d2v / (S->ssp[gb][row] + S->ssp[gb][jj] + EPSF) + S->smaM[gb][jj];
      float mx = rmax16(comp);
      float ex = expf(comp - mx);
      float sm = rsum16(ex);
      float mix = ex / sm;
      S->smix[gb][row][jj] = mix;
      float msp = rsum16(mix * S->ssp[gb][jj]);
      float mms = rsum16(mix * S->smaM[gb][jj]);
      if ((lane & 15) == 0){ S->sms[gb][row] = msp; S->smm[gb][row] = mms; }
    }
    __syncthreads(); // S11
    if (g < 2){
      float rl = S->srl[g];
      float cr[16];
      #pragma unroll
      for (int c = 0; c < 16; c++) cr[c] = S->sc[g][c][ht];
      #pragma unroll
      for (int i = 0; i < 16; i++){
        const float4* mr = (const float4*)S->smix[g][i];
        float4 m0 = mr[0], m1 = mr[1], m2v = mr[2], m3 = mr[3];
        float mc = m0.x*cr[0]+m0.y*cr[1]+m0.z*cr[2]+m0.w*cr[3]
                 + m1.x*cr[4]+m1.y*cr[5]+m1.z*cr[6]+m1.w*cr[7]
                 + m2v.x*cr[8]+m2v.y*cr[9]+m2v.z*cr[10]+m2v.w*cr[11]
                 + m3.x*cr[12]+m3.y*cr[13]+m3.z*cr[14]+m3.w*cr[15];
        S->sc[g][i][ht] = (1.f-rl)*cr[i] + rl*mc;
      }
    }
    if (g == 2 && ht < 32){
      const int gb = lane >> 4;
      const int c  = lane & 15;
      float rl2 = S->srl[gb];
      float sp = S->ssp[gb][c];
      float m  = S->smaM[gb][c];
      float sp2 = (1.f-rl2)*sp + rl2*S->sms[gb][c];
      float m2  = (1.f-rl2)*m  + rl2*S->smm[gb][c];
      float score = m2 + logf(1.f/(sp2+EPSF)+EPSF);
      float mx = rmax16(score);
      float ex = expf(score - mx);
      float sm = rsum16(ex);
      float ca = ex / sm;
      S->ssp[gb][c] = sp2*(1.f - 0.05f*ca*S->sval[gb]) + EPSF;
      S->smaM[gb][c] = m2;
    }
    __syncthreads(); // S12
  }

  // ---- epilogue ----
  if (g == 2 && ht < 32){
    const int gb = lane >> 4;
    const int c  = lane & 15;
    float sp = S->ssp[gb][c];
    float m  = S->smaM[gb][c];
    float score = m + logf(1.f/(sp+EPSF)+EPSF);
    float mx = rmax16(score);
    float ex = expf(score - mx);
    float sm = rsum16(ex);
    float a  = ex / sm;
    S->sal[gb][c] = a;
    float u   = rsum16(a*sp);
    float ent = rsum16(-a*logf(fmaxf(a,1e-8f)));
    float mm2 = rmax16(m);
    float en  = mm2 + logf(rsum16(expf(m - mm2)));
    float bv = a;
    int   bi = c;
    #pragma unroll
    for (int o = 8; o; o >>= 1){
      float ov = __shfl_xor_sync(0xffffffffu, bv, o);
      int   oi = __shfl_xor_sync(0xffffffffu, bi, o);
      if (ov > bv || (ov == bv && oi < bi)){ bv = ov; bi = oi; }
    }
    if (c == 0){
      S->sciT[256][gb] = u; S->sciT[258][gb] = en; S->sciT[259][gb] = ent; S->sidx[gb] = bi;
    }
  }
  __syncthreads();
  if (g < 2){
    float core = 0.f;
    #pragma unroll
    for (int c = 0; c < 16; c++) core += S->sal[g][c] * S->sc[g][c][ht];
    float dv = 0.f;
    #pragma unroll
    for (int c = 0; c < 16; c++){ float dd = S->sc[g][c][ht] - core; dv += S->sal[g][c]*dd*dd; }
    dv = rsum32(dv);
    if (lane == 0) S->sred[g][wg][2] = dv;
    float strong = S->sc[g][S->sidx[g]][ht];
    S->sciT[ht][g] = core;
    S->sciT[128+ht][g] = strong;
  }
  __syncthreads();
  if (tid < 2)
    S->sciT[257][tid] = (S->sred[tid][0][2]+S->sred[tid][1][2]+S->sred[tid][2][2]+S->sred[tid][3][2]) * (1.f/128.f);
  __syncthreads();
  {
    u64 ax[2] = {0,0}, ay[2] = {0,0};
    const int lo = isl * 16;
    #pragma unroll
    for (int r = 0; r < 16; r++){
      const int i = lo + r;
      ulonglong2 w = *(const ulonglong2*)&cw1[i*128 + j4*4];
      float2 x = *(const float2*)&S->sciT[i][0];
      u64 p0 = pack2(x.x), p1 = pack2(x.y);
      fma2(ax[0], p0, w.x); fma2(ay[0], p0, w.y);
      fma2(ax[1], p1, w.x); fma2(ay[1], p1, w.y);
    }
    if (isl < 4){
      const int i = 256 + isl;
      ulonglong2 w = *(const ulonglong2*)&cw1[i*128 + j4*4];
      float2 x = *(const float2*)&S->sciT[i][0];
      u64 p0 = pack2(x.x), p1 = pack2(x.y);
      fma2(ax[0], p0, w.x); fma2(ay[0], p0, w.y);
      fma2(ax[1], p1, w.x); fma2(ay[1], p1, w.y);
    }
    #pragma unroll
    for (int b2 = 0; b2 < 2; b2++){
      float2 l = unpack2(ax[b2]), h2 = unpack2(ay[b2]);
      *(float4*)&S->sbuf[isl][b2][j4*4] = make_float4(l.x, l.y, h2.x, h2.y);
    }
  }
  __syncthreads();
  if (g < 2){
    float s = cb1[ht];
    #pragma unroll
    for (int k = 0; k < 16; k++) s += S->sbuf[k][g][ht];
    S->sh1T[ht][g] = 0.5f * s * (1.f + erff(s * 0.70710678118654752440f));
  }
  __syncthreads();
  if (g < 2 && ht < 8){
    float s = cb2[ht];
    #pragma unroll 4
    for (int i = 0; i < 128; i++) s += S->sh1T[i][g] * cw2[i*8 + ht];
    out[b*8 + ht] = s;
  }
}

extern "C" void kernel_launch(void* const* d_in, const int* in_sizes, int n_in,
                              void* d_out, int out_size){
  (void)in_sizes; (void)n_in; (void)out_size;
  cudaFuncSetAttribute(cfrm_kernel, cudaFuncAttributeMaxDynamicSharedMemorySize, (int)sizeof(Smem));
  cfrm_kernel<<<64, 512, sizeof(Smem)>>>(
    (const int*)  d_in[0],  (const float*)d_in[1],  (const float*)d_in[2],  (const float*)d_in[3],
    (const float*)d_in[4],  (const float*)d_in[5],  (const float*)d_in[6],  (const float*)d_in[7],
    (const float*)d_in[8],  (const float*)d_in[9],  (const float*)d_in[10], (const float*)d_in[11],
    (const float*)d_in[12], (const float*)d_in[13], (const float*)d_in[14], (const float*)d_in[15],
    (const float*)d_in[16], (const float*)d_in[17], (const float*)d_in[18], (const float*)d_in[19],
    (const float*)d_in[20], (const float*)d_in[21], (const float*)d_in[22], (const float*)d_in[23],
    (const float*)d_in[24], (const float*)d_in[25], (const float*)d_in[26], (const float*)d_in[27],
    (float*)d_out);
}